// round 16
// baseline (speedup 1.0000x reference)
#include <cuda_runtime.h>
#include <cuda_bf16.h>
#include <cfloat>
#include <math.h>

// embed (8,4096,768) f32, centers (2048,768) f32 -> argmin_c ||x-c|| as f32 (8*4096)
// Phase 0: convert X, C to bf16 scratch; ||c||^2 in fp64.
// Phase 1: 1-pass bf16 mma.sync (m16n8k16) GEMM, depth-2 cp.async ring with a
//          single barrier per KT=128 tile, 2 CTAs/SM; top-4 per token.
// Phase 2a: fp32 refine of the 4 candidates; clear-gap tokens decided.
// Phase 2b: fp64 + reference-fp32-bit-replay (round-6 proven) for flagged ties.

#define D_FIXED 768
#define C_FIXED 2048
#define N_FIXED 32768

#define BM 128
#define BN 64
#define KT 128                  // k elements per tile (256 B rows)
#define NKT (D_FIXED / KT)      // 6
#define NCT (C_FIXED / BN)      // 32
#define NTILES (NCT * NKT)      // 192
#define SAB 272                 // smem row stride in bytes (17 x 16B, conflict-free)
#define NTHREADS 256
#define TOPK 4

#define OFF_A    0
#define OFF_B    34816          // A tile 128*272 = 34816 B
#define STG_B    52224          // + B tile 64*272 = 17408 B
#define NSTG     2
#define SMEM_TOTAL (NSTG * STG_B)       // 104448 B -> 2 CTAs/SM

__device__ float  g_csq[C_FIXED];
__device__ double g_csqd[C_FIXED];
__device__ int    g_topk[N_FIXED * TOPK];
__device__ int    g_flag[N_FIXED];
__device__ __nv_bfloat16 g_xbf[(size_t)N_FIXED * D_FIXED];
__device__ __nv_bfloat16 g_cbf[(size_t)C_FIXED * D_FIXED];

__device__ __forceinline__ unsigned sptr(const void* p) {
    return (unsigned)__cvta_generic_to_shared(p);
}
__device__ __forceinline__ void cp16(unsigned dst, const void* src) {
    asm volatile("cp.async.cg.shared.global [%0], [%1], 16;"
                 :: "r"(dst), "l"(src) : "memory");
}
__device__ __forceinline__ void cp_commit() {
    asm volatile("cp.async.commit_group;" ::: "memory");
}
template<int Nq>
__device__ __forceinline__ void cp_wait() {
    asm volatile("cp.async.wait_group %0;" :: "n"(Nq) : "memory");
}
__device__ __forceinline__ void ldsm4(unsigned* d, unsigned addr) {
    asm volatile("ldmatrix.sync.aligned.m8n8.x4.shared.b16 {%0,%1,%2,%3}, [%4];"
                 : "=r"(d[0]), "=r"(d[1]), "=r"(d[2]), "=r"(d[3]) : "r"(addr));
}
__device__ __forceinline__ void mma_bf16(float* d, const unsigned* a,
                                         unsigned b0, unsigned b1) {
    asm volatile(
        "mma.sync.aligned.m16n8k16.row.col.f32.bf16.bf16.f32 "
        "{%0,%1,%2,%3}, {%4,%5,%6,%7}, {%8,%9}, {%0,%1,%2,%3};"
        : "+f"(d[0]), "+f"(d[1]), "+f"(d[2]), "+f"(d[3])
        : "r"(a[0]), "r"(a[1]), "r"(a[2]), "r"(a[3]), "r"(b0), "r"(b1));
}
__device__ __forceinline__ bool lt(float v, int i, float w, int j) {
    return v < w || (v == w && i < j);
}

// ---------------- prologue kernels ----------------
__global__ void cvt_bf16_kernel(const float* __restrict__ src,
                                __nv_bfloat16* __restrict__ dst, int n4) {
    int i = blockIdx.x * blockDim.x + threadIdx.x;
    if (i >= n4) return;
    float4 v = reinterpret_cast<const float4*>(src)[i];
    __nv_bfloat162 p0, p1;
    p0.x = __float2bfloat16_rn(v.x); p0.y = __float2bfloat16_rn(v.y);
    p1.x = __float2bfloat16_rn(v.z); p1.y = __float2bfloat16_rn(v.w);
    reinterpret_cast<__nv_bfloat162*>(dst)[2 * i + 0] = p0;
    reinterpret_cast<__nv_bfloat162*>(dst)[2 * i + 1] = p1;
}

__global__ void csq_kernel(const float* __restrict__ centers, int C, int D) {
    int warp = (blockIdx.x * blockDim.x + threadIdx.x) >> 5;
    int lane = threadIdx.x & 31;
    if (warp >= C) return;
    const float* row = centers + (size_t)warp * D;
    double s = 0.0;
    for (int k = lane; k < D; k += 32) {
        double v = (double)row[k];
        s = fma(v, v, s);
    }
    #pragma unroll
    for (int o = 16; o > 0; o >>= 1)
        s += __shfl_down_sync(0xffffffffu, s, o);
    if (lane == 0) { g_csqd[warp] = s; g_csq[warp] = (float)s; }
}

// ---------------- depth-2 single-barrier bf16 rank kernel ----------------
__device__ __forceinline__ void stage_load(
    unsigned sb, int s, int it, int row0, int t,
    const __nv_bfloat16* __restrict__ xbf,
    const __nv_bfloat16* __restrict__ cbf) {
    const int ci = it / NKT, kt = it % NKT;
    const unsigned stg = sb + (unsigned)s * STG_B;
    const int ct0 = ci * BN;
    // A: 128 rows x 16 x 16B = 2048 cp16
    #pragma unroll
    for (int i = 0; i < 8; i++) {
        const int c   = t + i * NTHREADS;
        const int r   = c >> 4;
        const int seg = c & 15;
        cp16(stg + OFF_A + (unsigned)(r * SAB + seg * 16),
             xbf + (size_t)(row0 + r) * D_FIXED + kt * KT + seg * 8);
    }
    // B: 64 rows x 16 x 16B = 1024 cp16
    #pragma unroll
    for (int i = 0; i < 4; i++) {
        const int c   = t + i * NTHREADS;
        const int r   = c >> 4;
        const int seg = c & 15;
        cp16(stg + OFF_B + (unsigned)(r * SAB + seg * 16),
             cbf + (size_t)(ct0 + r) * D_FIXED + kt * KT + seg * 8);
    }
}

__global__ __launch_bounds__(NTHREADS, 2)
void rank_kernel(const __nv_bfloat16* __restrict__ xbf,
                 const __nv_bfloat16* __restrict__ cbf) {
    extern __shared__ char smem[];
    const unsigned sb = sptr(smem);
    float* redV = (float*)smem;                 // aliases stage 0, used post-loop
    int*   redI = (int*)(smem + BM * 16 * 4);

    const int t    = threadIdx.x;
    const int lane = t & 31;
    const int wid  = t >> 5;
    const int warp_m = wid & 3;
    const int warp_n = wid >> 2;
    const int row0 = blockIdx.x * BM;

    const int a_row = lane & 15;
    const int a_k   = (lane >> 4) * 16;
    unsigned aoff[2];
    #pragma unroll
    for (int mt = 0; mt < 2; mt++)
        aoff[mt] = (unsigned)((warp_m * 32 + mt * 16 + a_row) * SAB + a_k);

    const int g     = lane >> 3;
    const int b_row = (g == 0) ? lane : (g == 1) ? lane - 8
                    : (g == 2) ? lane - 8 : lane - 16;
    const int b_k   = (g & 1) * 16;
    unsigned boff[2];
    #pragma unroll
    for (int p = 0; p < 2; p++)
        boff[p] = (unsigned)((warp_n * 32 + p * 16 + b_row) * SAB + b_k);

    float v1[4], v2[4];
    int   i1[4], i2[4];
    #pragma unroll
    for (int s = 0; s < 4; s++) {
        v1[s] = FLT_MAX; v2[s] = FLT_MAX;
        i1[s] = 0x7fffffff; i2[s] = 0x7fffffff;
    }

    float acc[2][4][4];

    stage_load(sb, 0, 0, row0, t, xbf, cbf);
    cp_commit();

    for (int it = 0; it < NTILES; it++) {
        const int s  = it & 1;
        const int kt = it % NKT;
        const int ci = it / NKT;

        cp_wait<0>();            // tile it landed (per-thread)
        __syncthreads();         // all threads: tile it visible; buf s^1 free

        if (it + 1 < NTILES) {   // safe: everyone finished reading s^1 last iter
            stage_load(sb, s ^ 1, it + 1, row0, t, xbf, cbf);
            cp_commit();
        }

        if (kt == 0) {
            #pragma unroll
            for (int mt = 0; mt < 2; mt++)
                #pragma unroll
                for (int nt = 0; nt < 4; nt++)
                    #pragma unroll
                    for (int e = 0; e < 4; e++)
                        acc[mt][nt][e] = 0.f;
        }

        const unsigned stg = sb + (unsigned)s * STG_B;
        #pragma unroll
        for (int kk = 0; kk < KT / 16; kk++) {       // 8 k-chunks
            const unsigned kb = (unsigned)(kk * 32);
            unsigned a[2][4];
            #pragma unroll
            for (int mt = 0; mt < 2; mt++)
                ldsm4(a[mt], stg + OFF_A + aoff[mt] + kb);
            #pragma unroll
            for (int p = 0; p < 2; p++) {
                unsigned b[4];
                ldsm4(b, stg + OFF_B + boff[p] + kb);
                #pragma unroll
                for (int h = 0; h < 2; h++) {
                    const int nt = p * 2 + h;
                    #pragma unroll
                    for (int mt = 0; mt < 2; mt++)
                        mma_bf16(acc[mt][nt], a[mt], b[h*2], b[h*2+1]);
                }
            }
        }

        if (kt == NKT - 1) {
            #pragma unroll
            for (int mt = 0; mt < 2; mt++)
                #pragma unroll
                for (int e = 0; e < 4; e++) {
                    const int slot = mt * 2 + (e >> 1);
                    #pragma unroll
                    for (int nt = 0; nt < 4; nt++) {
                        const int cidx = ci * BN + warp_n * 32 + nt * 8
                                       + 2 * (lane & 3) + (e & 1);
                        const float sc = fmaf(-2.f, acc[mt][nt][e], __ldg(&g_csq[cidx]));
                        if (lt(sc, cidx, v1[slot], i1[slot])) {
                            v2[slot] = v1[slot]; i2[slot] = i1[slot];
                            v1[slot] = sc;       i1[slot] = cidx;
                        } else if (lt(sc, cidx, v2[slot], i2[slot])) {
                            v2[slot] = sc; i2[slot] = cidx;
                        }
                    }
                }
        }
    }
    __syncthreads();   // protect aliased reduction arrays

    const int contrib = warp_n * 4 + (lane & 3);
    #pragma unroll
    for (int slot = 0; slot < 4; slot++) {
        const int mt = slot >> 1, eh = slot & 1;
        const int r = warp_m * 32 + mt * 16 + eh * 8 + (lane >> 2);
        redV[r * 16 + contrib * 2 + 0] = v1[slot];
        redI[r * 16 + contrib * 2 + 0] = i1[slot];
        redV[r * 16 + contrib * 2 + 1] = v2[slot];
        redI[r * 16 + contrib * 2 + 1] = i2[slot];
    }
    __syncthreads();

    if (t < BM) {
        float bv[TOPK];
        int   bi[TOPK];
        #pragma unroll
        for (int q = 0; q < TOPK; q++) { bv[q] = FLT_MAX; bi[q] = 0x7fffffff; }
        #pragma unroll
        for (int e = 0; e < 16; e++) {
            float v = redV[t * 16 + e];
            int   i = redI[t * 16 + e];
            #pragma unroll
            for (int q = 0; q < TOPK; q++) {
                if (lt(v, i, bv[q], bi[q])) {
                    float tv = bv[q]; int ti = bi[q];
                    bv[q] = v; bi[q] = i;
                    v = tv; i = ti;
                }
            }
        }
        #pragma unroll
        for (int q = 0; q < TOPK; q++)
            g_topk[(row0 + t) * TOPK + q] = bi[q];
    }
}

// ---------------- phase 2a: fp32 refine, flag near-ties ----------------
__global__ __launch_bounds__(256)
void refine_fast_kernel(const float* __restrict__ X,
                        const float* __restrict__ Cent,
                        float* __restrict__ out, int N, int D) {
    const int tok  = (blockIdx.x * blockDim.x + threadIdx.x) >> 5;
    const int lane = threadIdx.x & 31;
    if (tok >= N) return;

    int cand[TOPK];
    #pragma unroll
    for (int q = 0; q < TOPK; q++) cand[q] = g_topk[tok * TOPK + q];

    const float* x = X + (size_t)tok * D;
    float x2 = 0.f, cr[TOPK] = {0.f, 0.f, 0.f, 0.f};
    #pragma unroll
    for (int i = 0; i < 6; i++) {
        const int k = i * 128 + lane * 4;
        const float4 xv = *reinterpret_cast<const float4*>(x + k);
        x2 = fmaf(xv.x, xv.x, fmaf(xv.y, xv.y, fmaf(xv.z, xv.z, fmaf(xv.w, xv.w, x2))));
        #pragma unroll
        for (int q = 0; q < TOPK; q++) {
            const float4 cv = *reinterpret_cast<const float4*>(
                Cent + (size_t)cand[q] * D + k);
            cr[q] = fmaf(xv.x, cv.x, fmaf(xv.y, cv.y,
                     fmaf(xv.z, cv.z, fmaf(xv.w, cv.w, cr[q]))));
        }
    }
    #pragma unroll
    for (int o = 16; o > 0; o >>= 1) {
        x2 += __shfl_down_sync(0xffffffffu, x2, o);
        #pragma unroll
        for (int q = 0; q < TOPK; q++)
            cr[q] += __shfl_down_sync(0xffffffffu, cr[q], o);
    }
    if (lane == 0) {
        float sv[TOPK], dv[TOPK];
        #pragma unroll
        for (int q = 0; q < TOPK; q++) {
            const float c2 = (float)g_csqd[cand[q]];
            float sq = __fsub_rn(__fadd_rn(x2, c2), __fmul_rn(2.0f, cr[q]));
            sq = fmaxf(sq, 0.f);
            sv[q] = sq;
            dv[q] = __fsqrt_rn(sq);
        }
        float bd = dv[0]; int bi = cand[0]; float bs = sv[0];
        #pragma unroll
        for (int q = 1; q < TOPK; q++)
            if (dv[q] < bd || (dv[q] == bd && cand[q] < bi)) {
                bd = dv[q]; bi = cand[q]; bs = sv[q];
            }
        float s2nd = FLT_MAX;
        #pragma unroll
        for (int q = 0; q < TOPK; q++)
            if (cand[q] != bi && sv[q] < s2nd) s2nd = sv[q];

        if (s2nd - bs > 0.01f) {
            out[tok] = (float)bi;
            g_flag[tok] = 0;
        } else {
            g_flag[tok] = 1;
        }
    }
}

// ---------------- phase 2b: exact fp64 + bit-replay for flagged ties ----------------
__global__ __launch_bounds__(256)
void refine_exact_kernel(const float* __restrict__ X,
                         const float* __restrict__ Cent,
                         float* __restrict__ out, int N, int D) {
    const int tok  = (blockIdx.x * blockDim.x + threadIdx.x) >> 5;
    const int lane = threadIdx.x & 31;
    if (tok >= N) return;
    if (g_flag[tok] == 0) return;

    int cand[TOPK];
    #pragma unroll
    for (int q = 0; q < TOPK; q++) cand[q] = g_topk[tok * TOPK + q];

    const float* x = X + (size_t)tok * D;
    double x2 = 0.0, cr[TOPK] = {0.0, 0.0, 0.0, 0.0};
    for (int k = lane; k < D; k += 32) {
        const double xv = (double)x[k];
        x2 = fma(xv, xv, x2);
        #pragma unroll
        for (int q = 0; q < TOPK; q++)
            cr[q] = fma(xv, (double)Cent[(size_t)cand[q] * D + k], cr[q]);
    }
    #pragma unroll
    for (int o = 16; o > 0; o >>= 1) {
        x2 += __shfl_down_sync(0xffffffffu, x2, o);
        #pragma unroll
        for (int q = 0; q < TOPK; q++)
            cr[q] += __shfl_down_sync(0xffffffffu, cr[q], o);
    }
    if (lane == 0) {
        const float x2f = (float)x2;
        float bd = FLT_MAX;
        int   bi = 0x7fffffff;
        #pragma unroll
        for (int q = 0; q < TOPK; q++) {
            const float c2  = (float)g_csqd[cand[q]];
            const float crf = (float)cr[q];
            float sq = __fsub_rn(__fadd_rn(x2f, c2), __fmul_rn(2.0f, crf));
            sq = fmaxf(sq, 0.f);
            const float d = __fsqrt_rn(sq);
            if (d < bd || (d == bd && cand[q] < bi)) { bd = d; bi = cand[q]; }
        }
        out[tok] = (float)bi;
    }
}

extern "C" void kernel_launch(void* const* d_in, const int* in_sizes, int n_in,
                              void* d_out, int out_size) {
    const float* embed   = (const float*)d_in[0];
    const float* centers = (const float*)d_in[1];
    float* out = (float*)d_out;

    const int D = D_FIXED;
    const int N = in_sizes[0] / D;   // 32768
    const int C = in_sizes[1] / D;   // 2048

    void *pxbf, *pcbf;
    cudaGetSymbolAddress(&pxbf, g_xbf);
    cudaGetSymbolAddress(&pcbf, g_cbf);

    static bool attr_set = false;
    if (!attr_set) {
        cudaFuncSetAttribute(rank_kernel,
                             cudaFuncAttributeMaxDynamicSharedMemorySize, SMEM_TOTAL);
        attr_set = true;
    }

    // phase 0: bf16 conversion + c^2
    {
        const int n4x = N * D / 4;
        cvt_bf16_kernel<<<(n4x + 255) / 256, 256>>>(embed, (__nv_bfloat16*)pxbf, n4x);
        const int n4c = C * D / 4;
        cvt_bf16_kernel<<<(n4c + 255) / 256, 256>>>(centers, (__nv_bfloat16*)pcbf, n4c);
        csq_kernel<<<(C * 32 + 255) / 256, 256>>>(centers, C, D);
    }
    // phase 1: 1-pass bf16 tensor-core ranking (top-4), single-barrier tiles
    rank_kernel<<<N / BM, NTHREADS, SMEM_TOTAL>>>(
        (const __nv_bfloat16*)pxbf, (const __nv_bfloat16*)pcbf);
    // phase 2: fp32 fast refine, then exact fp64 bit-replay on flagged ties
    refine_fast_kernel<<<(N * 32 + 255) / 256, 256>>>(embed, centers, out, N, D);
    refine_exact_kernel<<<(N * 32 + 255) / 256, 256>>>(embed, centers, out, N, D);
}

// round 17
// speedup vs baseline: 1.1909x; 1.1909x over previous
#include <cuda_runtime.h>
#include <cuda_bf16.h>
#include <cfloat>
#include <math.h>

// embed (8,4096,768) f32, centers (2048,768) f32 -> argmin_c ||x-c|| as f32 (8*4096)
// Phase 0: convert X, C to bf16 scratch; ||c||^2 in fp64.
// Phase 1: 1-pass bf16 mma.sync (m16n8k16) GEMM, depth-3 cp.async ring,
//          warp tile 32x64 (BN=128) to cut smem bytes/MAC, 2 CTAs/SM; top-4/token.
// Phase 2a: fp32 refine of the 4 candidates; clear-gap tokens decided.
// Phase 2b: fp64 + reference-fp32-bit-replay (round-6 proven) for flagged ties.

#define D_FIXED 768
#define C_FIXED 2048
#define N_FIXED 32768

#define BM 128
#define BN 128                  // clusters per chunk (warp tile 32x64)
#define KT 64
#define NKT (D_FIXED / KT)      // 12
#define NCT (C_FIXED / BN)      // 16
#define NTILES (NCT * NKT)      // 192
#define SAH 72                  // smem row stride in halves (144 B)
#define NTHREADS 256
#define TOPK 4

#define OFF_A    0
#define OFF_B    18432          // A tile 128*144 = 18432 B
#define STG_B    36864          // + B tile 128*144 = 18432 B
#define NSTG     3
#define SMEM_TOTAL (NSTG * STG_B)       // 110592 B -> 2 CTAs/SM (221 KB)

__device__ float  g_csq[C_FIXED];
__device__ double g_csqd[C_FIXED];
__device__ int    g_topk[N_FIXED * TOPK];
__device__ int    g_flag[N_FIXED];
__device__ __nv_bfloat16 g_xbf[(size_t)N_FIXED * D_FIXED];
__device__ __nv_bfloat16 g_cbf[(size_t)C_FIXED * D_FIXED];

__device__ __forceinline__ unsigned sptr(const void* p) {
    return (unsigned)__cvta_generic_to_shared(p);
}
__device__ __forceinline__ void cp16(unsigned dst, const void* src) {
    asm volatile("cp.async.cg.shared.global [%0], [%1], 16;"
                 :: "r"(dst), "l"(src) : "memory");
}
__device__ __forceinline__ void cp_commit() {
    asm volatile("cp.async.commit_group;" ::: "memory");
}
template<int Nq>
__device__ __forceinline__ void cp_wait() {
    asm volatile("cp.async.wait_group %0;" :: "n"(Nq) : "memory");
}
__device__ __forceinline__ void ldsm4(unsigned* d, unsigned addr) {
    asm volatile("ldmatrix.sync.aligned.m8n8.x4.shared.b16 {%0,%1,%2,%3}, [%4];"
                 : "=r"(d[0]), "=r"(d[1]), "=r"(d[2]), "=r"(d[3]) : "r"(addr));
}
__device__ __forceinline__ void mma_bf16(float* d, const unsigned* a,
                                         unsigned b0, unsigned b1) {
    asm volatile(
        "mma.sync.aligned.m16n8k16.row.col.f32.bf16.bf16.f32 "
        "{%0,%1,%2,%3}, {%4,%5,%6,%7}, {%8,%9}, {%0,%1,%2,%3};"
        : "+f"(d[0]), "+f"(d[1]), "+f"(d[2]), "+f"(d[3])
        : "r"(a[0]), "r"(a[1]), "r"(a[2]), "r"(a[3]), "r"(b0), "r"(b1));
}
__device__ __forceinline__ bool lt(float v, int i, float w, int j) {
    return v < w || (v == w && i < j);
}

// ---------------- prologue kernels ----------------
__global__ void cvt_bf16_kernel(const float* __restrict__ src,
                                __nv_bfloat16* __restrict__ dst, int n4) {
    int i = blockIdx.x * blockDim.x + threadIdx.x;
    if (i >= n4) return;
    float4 v = reinterpret_cast<const float4*>(src)[i];
    __nv_bfloat162 p0, p1;
    p0.x = __float2bfloat16_rn(v.x); p0.y = __float2bfloat16_rn(v.y);
    p1.x = __float2bfloat16_rn(v.z); p1.y = __float2bfloat16_rn(v.w);
    reinterpret_cast<__nv_bfloat162*>(dst)[2 * i + 0] = p0;
    reinterpret_cast<__nv_bfloat162*>(dst)[2 * i + 1] = p1;
}

__global__ void csq_kernel(const float* __restrict__ centers, int C, int D) {
    int warp = (blockIdx.x * blockDim.x + threadIdx.x) >> 5;
    int lane = threadIdx.x & 31;
    if (warp >= C) return;
    const float* row = centers + (size_t)warp * D;
    double s = 0.0;
    for (int k = lane; k < D; k += 32) {
        double v = (double)row[k];
        s = fma(v, v, s);
    }
    #pragma unroll
    for (int o = 16; o > 0; o >>= 1)
        s += __shfl_down_sync(0xffffffffu, s, o);
    if (lane == 0) { g_csqd[warp] = s; g_csq[warp] = (float)s; }
}

// ---------------- depth-3 pipelined bf16 rank kernel ----------------
__device__ __forceinline__ void stage_load(
    unsigned sb, int s, int it, int row0, int t,
    const __nv_bfloat16* __restrict__ xbf,
    const __nv_bfloat16* __restrict__ cbf) {
    const int ci = it / NKT, kt = it % NKT;
    const unsigned stg = sb + (unsigned)s * STG_B;
    const int ct0 = ci * BN;
    // A: 128 rows x 8 x 16B = 1024 cp16
    #pragma unroll
    for (int i = 0; i < 4; i++) {
        const int c   = t + i * NTHREADS;
        const int r   = c >> 3;
        const int seg = c & 7;
        cp16(stg + OFF_A + (unsigned)(r * (SAH * 2) + seg * 16),
             xbf + (size_t)(row0 + r) * D_FIXED + kt * KT + seg * 8);
    }
    // B: 128 rows x 8 x 16B = 1024 cp16
    #pragma unroll
    for (int i = 0; i < 4; i++) {
        const int c   = t + i * NTHREADS;
        const int r   = c >> 3;
        const int seg = c & 7;
        cp16(stg + OFF_B + (unsigned)(r * (SAH * 2) + seg * 16),
             cbf + (size_t)(ct0 + r) * D_FIXED + kt * KT + seg * 8);
    }
}

__global__ __launch_bounds__(NTHREADS, 2)
void rank_kernel(const __nv_bfloat16* __restrict__ xbf,
                 const __nv_bfloat16* __restrict__ cbf) {
    extern __shared__ char smem[];
    const unsigned sb = sptr(smem);
    float* redV = (float*)smem;                 // aliases stage 0, post-loop only
    int*   redI = (int*)(smem + BM * 16 * 4);

    const int t    = threadIdx.x;
    const int lane = t & 31;
    const int wid  = t >> 5;
    const int warp_m = wid & 3;                 // 4 m-warps (32 tokens each)
    const int warp_n = wid >> 2;                // 2 n-warps (64 clusters each)
    const int row0 = blockIdx.x * BM;

    const int a_row = lane & 15;
    const int a_k   = (lane >> 4) * 16;
    unsigned aoff[2];
    #pragma unroll
    for (int mt = 0; mt < 2; mt++)
        aoff[mt] = (unsigned)((warp_m * 32 + mt * 16 + a_row) * (SAH * 2) + a_k);

    const int g     = lane >> 3;
    const int b_row = (g == 0) ? lane : (g == 1) ? lane - 8
                    : (g == 2) ? lane - 8 : lane - 16;
    const int b_k   = (g & 1) * 16;
    unsigned boff[4];
    #pragma unroll
    for (int p = 0; p < 4; p++)
        boff[p] = (unsigned)((warp_n * 64 + p * 16 + b_row) * (SAH * 2) + b_k);

    float v1[4], v2[4];
    int   i1[4], i2[4];
    #pragma unroll
    for (int s = 0; s < 4; s++) {
        v1[s] = FLT_MAX; v2[s] = FLT_MAX;
        i1[s] = 0x7fffffff; i2[s] = 0x7fffffff;
    }

    float acc[2][8][4];

    stage_load(sb, 0, 0, row0, t, xbf, cbf);
    cp_commit();
    stage_load(sb, 1, 1, row0, t, xbf, cbf);
    cp_commit();

    int s = 0;
    for (int it = 0; it < NTILES; it++) {
        const int kt = it % NKT;
        const int ci = it / NKT;

        if (it == NTILES - 1) cp_wait<0>(); else cp_wait<1>();
        __syncthreads();

        if (kt == 0) {
            #pragma unroll
            for (int mt = 0; mt < 2; mt++)
                #pragma unroll
                for (int nt = 0; nt < 8; nt++)
                    #pragma unroll
                    for (int e = 0; e < 4; e++)
                        acc[mt][nt][e] = 0.f;
        }

        const unsigned stg = sb + (unsigned)s * STG_B;
        #pragma unroll
        for (int kk = 0; kk < KT / 16; kk++) {       // 4 k-chunks
            const unsigned kb = (unsigned)(kk * 32);
            unsigned a[2][4];
            #pragma unroll
            for (int mt = 0; mt < 2; mt++)
                ldsm4(a[mt], stg + OFF_A + aoff[mt] + kb);
            #pragma unroll
            for (int p = 0; p < 4; p++) {
                unsigned b[4];
                ldsm4(b, stg + OFF_B + boff[p] + kb);
                #pragma unroll
                for (int h = 0; h < 2; h++) {
                    const int nt = p * 2 + h;
                    #pragma unroll
                    for (int mt = 0; mt < 2; mt++)
                        mma_bf16(acc[mt][nt], a[mt], b[h*2], b[h*2+1]);
                }
            }
        }

        if (kt == NKT - 1) {
            #pragma unroll
            for (int mt = 0; mt < 2; mt++)
                #pragma unroll
                for (int e = 0; e < 4; e++) {
                    const int slot = mt * 2 + (e >> 1);
                    #pragma unroll
                    for (int nt = 0; nt < 8; nt++) {
                        const int cidx = ci * BN + warp_n * 64 + nt * 8
                                       + 2 * (lane & 3) + (e & 1);
                        const float sc = fmaf(-2.f, acc[mt][nt][e], __ldg(&g_csq[cidx]));
                        if (lt(sc, cidx, v1[slot], i1[slot])) {
                            v2[slot] = v1[slot]; i2[slot] = i1[slot];
                            v1[slot] = sc;       i1[slot] = cidx;
                        } else if (lt(sc, cidx, v2[slot], i2[slot])) {
                            v2[slot] = sc; i2[slot] = cidx;
                        }
                    }
                }
        }

        if (it + 2 < NTILES) {
            const int s2 = (s + 2 >= 3) ? (s - 1) : (s + 2);
            stage_load(sb, s2, it + 2, row0, t, xbf, cbf);
            cp_commit();
        }
        s = (s + 1 == 3) ? 0 : s + 1;
    }
    __syncthreads();   // protect aliased reduction arrays

    // 8 contributors (4 lane-groups x 2 warp_n) x top-2 per token
    const int contrib = warp_n * 4 + (lane & 3);
    #pragma unroll
    for (int slot = 0; slot < 4; slot++) {
        const int mt = slot >> 1, eh = slot & 1;
        const int r = warp_m * 32 + mt * 16 + eh * 8 + (lane >> 2);
        redV[r * 16 + contrib * 2 + 0] = v1[slot];
        redI[r * 16 + contrib * 2 + 0] = i1[slot];
        redV[r * 16 + contrib * 2 + 1] = v2[slot];
        redI[r * 16 + contrib * 2 + 1] = i2[slot];
    }
    __syncthreads();

    if (t < BM) {
        float bv[TOPK];
        int   bi[TOPK];
        #pragma unroll
        for (int q = 0; q < TOPK; q++) { bv[q] = FLT_MAX; bi[q] = 0x7fffffff; }
        #pragma unroll
        for (int e = 0; e < 16; e++) {
            float v = redV[t * 16 + e];
            int   i = redI[t * 16 + e];
            #pragma unroll
            for (int q = 0; q < TOPK; q++) {
                if (lt(v, i, bv[q], bi[q])) {
                    float tv = bv[q]; int ti = bi[q];
                    bv[q] = v; bi[q] = i;
                    v = tv; i = ti;
                }
            }
        }
        #pragma unroll
        for (int q = 0; q < TOPK; q++)
            g_topk[(row0 + t) * TOPK + q] = bi[q];
    }
}

// ---------------- phase 2a: fp32 refine, flag near-ties ----------------
__global__ __launch_bounds__(256)
void refine_fast_kernel(const float* __restrict__ X,
                        const float* __restrict__ Cent,
                        float* __restrict__ out, int N, int D) {
    const int tok  = (blockIdx.x * blockDim.x + threadIdx.x) >> 5;
    const int lane = threadIdx.x & 31;
    if (tok >= N) return;

    int cand[TOPK];
    #pragma unroll
    for (int q = 0; q < TOPK; q++) cand[q] = g_topk[tok * TOPK + q];

    const float* x = X + (size_t)tok * D;
    float x2 = 0.f, cr[TOPK] = {0.f, 0.f, 0.f, 0.f};
    #pragma unroll
    for (int i = 0; i < 6; i++) {
        const int k = i * 128 + lane * 4;
        const float4 xv = *reinterpret_cast<const float4*>(x + k);
        x2 = fmaf(xv.x, xv.x, fmaf(xv.y, xv.y, fmaf(xv.z, xv.z, fmaf(xv.w, xv.w, x2))));
        #pragma unroll
        for (int q = 0; q < TOPK; q++) {
            const float4 cv = *reinterpret_cast<const float4*>(
                Cent + (size_t)cand[q] * D + k);
            cr[q] = fmaf(xv.x, cv.x, fmaf(xv.y, cv.y,
                     fmaf(xv.z, cv.z, fmaf(xv.w, cv.w, cr[q]))));
        }
    }
    #pragma unroll
    for (int o = 16; o > 0; o >>= 1) {
        x2 += __shfl_down_sync(0xffffffffu, x2, o);
        #pragma unroll
        for (int q = 0; q < TOPK; q++)
            cr[q] += __shfl_down_sync(0xffffffffu, cr[q], o);
    }
    if (lane == 0) {
        float sv[TOPK], dv[TOPK];
        #pragma unroll
        for (int q = 0; q < TOPK; q++) {
            const float c2 = (float)g_csqd[cand[q]];
            float sq = __fsub_rn(__fadd_rn(x2, c2), __fmul_rn(2.0f, cr[q]));
            sq = fmaxf(sq, 0.f);
            sv[q] = sq;
            dv[q] = __fsqrt_rn(sq);
        }
        float bd = dv[0]; int bi = cand[0]; float bs = sv[0];
        #pragma unroll
        for (int q = 1; q < TOPK; q++)
            if (dv[q] < bd || (dv[q] == bd && cand[q] < bi)) {
                bd = dv[q]; bi = cand[q]; bs = sv[q];
            }
        float s2nd = FLT_MAX;
        #pragma unroll
        for (int q = 0; q < TOPK; q++)
            if (cand[q] != bi && sv[q] < s2nd) s2nd = sv[q];

        if (s2nd - bs > 0.01f) {
            out[tok] = (float)bi;
            g_flag[tok] = 0;
        } else {
            g_flag[tok] = 1;
        }
    }
}

// ---------------- phase 2b: exact fp64 + bit-replay for flagged ties ----------------
__global__ __launch_bounds__(256)
void refine_exact_kernel(const float* __restrict__ X,
                         const float* __restrict__ Cent,
                         float* __restrict__ out, int N, int D) {
    const int tok  = (blockIdx.x * blockDim.x + threadIdx.x) >> 5;
    const int lane = threadIdx.x & 31;
    if (tok >= N) return;
    if (g_flag[tok] == 0) return;

    int cand[TOPK];
    #pragma unroll
    for (int q = 0; q < TOPK; q++) cand[q] = g_topk[tok * TOPK + q];

    const float* x = X + (size_t)tok * D;
    double x2 = 0.0, cr[TOPK] = {0.0, 0.0, 0.0, 0.0};
    for (int k = lane; k < D; k += 32) {
        const double xv = (double)x[k];
        x2 = fma(xv, xv, x2);
        #pragma unroll
        for (int q = 0; q < TOPK; q++)
            cr[q] = fma(xv, (double)Cent[(size_t)cand[q] * D + k], cr[q]);
    }
    #pragma unroll
    for (int o = 16; o > 0; o >>= 1) {
        x2 += __shfl_down_sync(0xffffffffu, x2, o);
        #pragma unroll
        for (int q = 0; q < TOPK; q++)
            cr[q] += __shfl_down_sync(0xffffffffu, cr[q], o);
    }
    if (lane == 0) {
        const float x2f = (float)x2;
        float bd = FLT_MAX;
        int   bi = 0x7fffffff;
        #pragma unroll
        for (int q = 0; q < TOPK; q++) {
            const float c2  = (float)g_csqd[cand[q]];
            const float crf = (float)cr[q];
            float sq = __fsub_rn(__fadd_rn(x2f, c2), __fmul_rn(2.0f, crf));
            sq = fmaxf(sq, 0.f);
            const float d = __fsqrt_rn(sq);
            if (d < bd || (d == bd && cand[q] < bi)) { bd = d; bi = cand[q]; }
        }
        out[tok] = (float)bi;
    }
}

extern "C" void kernel_launch(void* const* d_in, const int* in_sizes, int n_in,
                              void* d_out, int out_size) {
    const float* embed   = (const float*)d_in[0];
    const float* centers = (const float*)d_in[1];
    float* out = (float*)d_out;

    const int D = D_FIXED;
    const int N = in_sizes[0] / D;   // 32768
    const int C = in_sizes[1] / D;   // 2048

    void *pxbf, *pcbf;
    cudaGetSymbolAddress(&pxbf, g_xbf);
    cudaGetSymbolAddress(&pcbf, g_cbf);

    static bool attr_set = false;
    if (!attr_set) {
        cudaFuncSetAttribute(rank_kernel,
                             cudaFuncAttributeMaxDynamicSharedMemorySize, SMEM_TOTAL);
        attr_set = true;
    }

    // phase 0: bf16 conversion + c^2
    {
        const int n4x = N * D / 4;
        cvt_bf16_kernel<<<(n4x + 255) / 256, 256>>>(embed, (__nv_bfloat16*)pxbf, n4x);
        const int n4c = C * D / 4;
        cvt_bf16_kernel<<<(n4c + 255) / 256, 256>>>(centers, (__nv_bfloat16*)pcbf, n4c);
        csq_kernel<<<(C * 32 + 255) / 256, 256>>>(centers, C, D);
    }
    // phase 1: 1-pass bf16 tensor-core ranking (top-4), 32x64 warp tiles
    rank_kernel<<<N / BM, NTHREADS, SMEM_TOTAL>>>(
        (const __nv_bfloat16*)pxbf, (const __nv_bfloat16*)pcbf);
    // phase 2: fp32 fast refine, then exact fp64 bit-replay on flagged ties
    refine_fast_kernel<<<(N * 32 + 255) / 256, 256>>>(embed, centers, out, N, D);
    refine_exact_kernel<<<(N * 32 + 255) / 256, 256>>>(embed, centers, out, N, D);
}